// round 7
// baseline (speedup 1.0000x reference)
#include <cuda_runtime.h>

// UniversalRNN: 2-layer tanh RNN (B=2048, T=512, IN=1, H=64) + FC(64->1).
// R5 -> R6 change: occupancy. R5 profile showed fma=26.6%, L1=75%, issue=41.5%,
// occ=12.5% -> latency-bound at 8 warps/SM. Split each CTA in two: NT=128,
// BB=8, grid=256, 2 CTAs/SM (126.6KB smem/SM). Same per-SM work and smem
// traffic, 2x warps for latency hiding. Thread tile stays 2 rows x 2 dims.

constexpr int Bq = 2048;
constexpr int Tt = 512;
constexpr int BB = 8;     // batch rows per CTA
constexpr int NT = 128;   // threads per CTA
constexpr int HP = 68;    // padded row pitch (floats)
constexpr int XS = 65;    // x chunk row pitch

// tanh via ex2/rcp approx: tanh(x) = 1 - 2/(exp2(2x*log2(e)) + 1), ~1e-6 abs err
__device__ __forceinline__ float fast_tanhf(float x) {
    float e;
    asm("ex2.approx.f32 %0, %1;" : "=f"(e) : "f"(x * 2.8853900817779268f));
    float r;
    asm("rcp.approx.f32 %0, %1;" : "=f"(r) : "f"(e + 1.0f));
    return fmaf(-2.0f, r, 1.0f);
}

// function, NOT a macro (macro param `w` was captured by `.w` member tokens)
__device__ __forceinline__ void fma4(float& acc, const float4& a, const float4& b) {
    acc = fmaf(a.x, b.x, acc);
    acc = fmaf(a.y, b.y, acc);
    acc = fmaf(a.z, b.z, acc);
    acc = fmaf(a.w, b.w, acc);
}

__global__ __launch_bounds__(NT, 2) void rnn_fused_kernel(
    const float* __restrict__ x,      // [B, T, 1]
    const float* __restrict__ Wih0,   // [64, 1]
    const float* __restrict__ Whh0,   // [64, 64]
    const float* __restrict__ bih0,   // [64]
    const float* __restrict__ bhh0,   // [64]
    const float* __restrict__ Wih1,   // [64, 64]
    const float* __restrict__ Whh1,   // [64, 64]
    const float* __restrict__ bih1,   // [64]
    const float* __restrict__ bhh1,   // [64]
    const float* __restrict__ Wfc,    // [1, 64]
    const float* __restrict__ bfc,    // [1]
    float* __restrict__ out)          // [B, 1]
{
    extern __shared__ float sm[];
    float* W0  = sm;                 // Whh0 [64][HP]
    float* Wi1 = W0  + 64 * HP;      // Wih1 [64][HP]
    float* Wh1 = Wi1 + 64 * HP;      // Whh1 [64][HP]
    float* h0s = Wh1 + 64 * HP;      // [2][BB][HP] double-buffered
    float* h1s = h0s + 2 * BB * HP;  // [2][BB][HP]
    float* xs  = h1s + 2 * BB * HP;  // [BB][XS] x chunk (64 timesteps)
    float* wfc = xs  + BB * XS;      // [64]

    const int tx = threadIdx.x;
    const int b0 = blockIdx.x * BB;

    // ---- stage weights into shared (padded pitch) ----
    for (int idx = tx; idx < 64 * 64; idx += NT) {
        int r = idx >> 6, c = idx & 63;
        W0 [r * HP + c] = Whh0[idx];
        Wi1[r * HP + c] = Wih1[idx];
        Wh1[r * HP + c] = Whh1[idx];
    }
    if (tx < 64) wfc[tx] = Wfc[tx];
    for (int idx = tx; idx < 2 * BB * HP; idx += NT) {
        h0s[idx] = 0.0f;
        h1s[idx] = 0.0f;
    }

    // thread tile: batch rows {bp, bp+4}, output dims {2dq, 2dq+1}
    const int bp = tx & 3;
    const int dq = tx >> 2;          // 0..31
    const int r0 = bp, r1 = bp + 4;
    const int i0 = 2 * dq;

    const float wxa = Wih0[i0], wxb = Wih0[i0 + 1];
    const float b0a = bih0[i0] + bhh0[i0];
    const float b0b = bih0[i0 + 1] + bhh0[i0 + 1];
    const float b1a = bih1[i0] + bhh1[i0];
    const float b1b = bih1[i0 + 1] + bhh1[i0 + 1];

    __syncthreads();

    int cur = 0;
    for (int t = 0; t < Tt; ++t) {
        // refill x chunk every 64 steps (prior step's end-barrier orders this)
        if ((t & 63) == 0) {
            #pragma unroll
            for (int j = 0; j < (BB * 64) / NT; ++j) {
                int idx = tx + j * NT;
                int r = idx >> 6, c = idx & 63;
                xs[r * XS + c] = x[(b0 + r) * Tt + t + c];
            }
            __syncthreads();
        }
        const int tc = t & 63;
        const float* h0c = h0s + cur * BB * HP;
        float*       h0n = h0s + (cur ^ 1) * BB * HP;
        const float* h1c = h1s + cur * BB * HP;
        float*       h1n = h1s + (cur ^ 1) * BB * HP;

        // ---- phase 1: layer-0 step  h0' = tanh(x*wih0 + b + Whh0 h0) ----
        const float xv0 = xs[r0 * XS + tc];
        const float xv1 = xs[r1 * XS + tc];
        float a00 = fmaf(xv0, wxa, b0a);
        float a01 = fmaf(xv0, wxb, b0b);
        float a10 = fmaf(xv1, wxa, b0a);
        float a11 = fmaf(xv1, wxb, b0b);
        #pragma unroll
        for (int q = 0; q < 16; ++q) {
            float4 ha = *(const float4*)(h0c + r0 * HP + 4 * q);
            float4 hb = *(const float4*)(h0c + r1 * HP + 4 * q);
            float4 wa = *(const float4*)(W0 + i0 * HP + 4 * q);
            float4 wb = *(const float4*)(W0 + (i0 + 1) * HP + 4 * q);
            fma4(a00, ha, wa); fma4(a01, ha, wb);
            fma4(a10, hb, wa); fma4(a11, hb, wb);
        }
        {
            float2 v0 = make_float2(fast_tanhf(a00), fast_tanhf(a01));
            float2 v1 = make_float2(fast_tanhf(a10), fast_tanhf(a11));
            *(float2*)(h0n + r0 * HP + i0) = v0;
            *(float2*)(h0n + r1 * HP + i0) = v1;
        }
        __syncthreads();

        // ---- phase 2: layer-1 step  h1' = tanh(Wih1 h0' + b + Whh1 h1) ----
        a00 = b1a; a01 = b1b; a10 = b1a; a11 = b1b;
        #pragma unroll
        for (int q = 0; q < 16; ++q) {
            float4 ga = *(const float4*)(h0n + r0 * HP + 4 * q);
            float4 gb = *(const float4*)(h0n + r1 * HP + 4 * q);
            float4 wa = *(const float4*)(Wi1 + i0 * HP + 4 * q);
            float4 wb = *(const float4*)(Wi1 + (i0 + 1) * HP + 4 * q);
            fma4(a00, ga, wa); fma4(a01, ga, wb);
            fma4(a10, gb, wa); fma4(a11, gb, wb);
            float4 ha = *(const float4*)(h1c + r0 * HP + 4 * q);
            float4 hb = *(const float4*)(h1c + r1 * HP + 4 * q);
            float4 va = *(const float4*)(Wh1 + i0 * HP + 4 * q);
            float4 vb = *(const float4*)(Wh1 + (i0 + 1) * HP + 4 * q);
            fma4(a00, ha, va); fma4(a01, ha, vb);
            fma4(a10, hb, va); fma4(a11, hb, vb);
        }
        {
            float2 v0 = make_float2(fast_tanhf(a00), fast_tanhf(a01));
            float2 v1 = make_float2(fast_tanhf(a10), fast_tanhf(a11));
            *(float2*)(h1n + r0 * HP + i0) = v0;
            *(float2*)(h1n + r1 * HP + i0) = v1;
        }
        __syncthreads();
        cur ^= 1;
    }

    // ---- FC head: out[b] = Wfc . h1_last[b] + bfc ----
    const float* h1f = h1s + cur * BB * HP;
    if (tx < BB) {
        float acc = bfc[0];
        #pragma unroll
        for (int k = 0; k < 64; ++k)
            acc = fmaf(h1f[tx * HP + k], wfc[k], acc);
        out[b0 + tx] = acc;
    }
}

extern "C" void kernel_launch(void* const* d_in, const int* in_sizes, int n_in,
                              void* d_out, int out_size) {
    (void)in_sizes; (void)n_in; (void)out_size;
    const float* x    = (const float*)d_in[0];
    const float* Wih0 = (const float*)d_in[1];
    const float* Whh0 = (const float*)d_in[2];
    const float* bih0 = (const float*)d_in[3];
    const float* bhh0 = (const float*)d_in[4];
    const float* Wih1 = (const float*)d_in[5];
    const float* Whh1 = (const float*)d_in[6];
    const float* bih1 = (const float*)d_in[7];
    const float* bhh1 = (const float*)d_in[8];
    const float* Wfc  = (const float*)d_in[9];
    const float* bfc  = (const float*)d_in[10];
    float* out = (float*)d_out;

    constexpr int SMEM_FLOATS = 3 * 64 * HP + 4 * BB * HP + BB * XS + 64;
    constexpr int SMEM_BYTES  = SMEM_FLOATS * 4;  // ~64.8KB -> 2 CTAs/SM

    cudaFuncSetAttribute(rnn_fused_kernel,
                         cudaFuncAttributeMaxDynamicSharedMemorySize, SMEM_BYTES);

    dim3 grid(Bq / BB), block(NT);   // 256 CTAs
    rnn_fused_kernel<<<grid, block, SMEM_BYTES>>>(
        x, Wih0, Whh0, bih0, bhh0, Wih1, Whh1, bih1, bhh1, Wfc, bfc, out);
}

// round 10
// speedup vs baseline: 1.0119x; 1.0119x over previous
#include <cuda_runtime.h>

// UniversalRNN: 2-layer tanh RNN (B=2048, T=512, IN=1, H=64) + FC(64->1).
// R7: R5/R6 profiles showed LSU-instruction-bound (L1=79%, fma=27%, issue=43%)
// at 8 warps/SM. This version: NT=512 (16 warps/SM, grid=128, 1 CTA/SM),
// k-split tile 2 rows x 4 dims x 16 k per thread (butterfly-shuffle reduce),
// packed fma.rn.f32x2 (halves FFMA issue), warp-broadcast weight loads.

constexpr int Bq = 2048;
constexpr int Tt = 512;
constexpr int BB = 16;    // batch rows per CTA
constexpr int NT = 512;   // threads per CTA (16 warps)
constexpr int HP = 68;    // padded row pitch (floats)
constexpr int XS = 65;    // x chunk row pitch

// tanh via ex2/rcp approx: tanh(x) = 1 - 2/(exp2(2x*log2(e)) + 1), ~1e-6 abs err
__device__ __forceinline__ float fast_tanhf(float x) {
    float e;
    asm("ex2.approx.f32 %0, %1;" : "=f"(e) : "f"(x * 2.8853900817779268f));
    float r;
    asm("rcp.approx.f32 %0, %1;" : "=f"(r) : "f"(e + 1.0f));
    return fmaf(-2.0f, r, 1.0f);
}

// packed 2xf32 fma (sm_100+ PTX only; ptxas will not auto-fuse)
__device__ __forceinline__ unsigned long long fma2(
    unsigned long long a, unsigned long long b, unsigned long long c) {
    unsigned long long d;
    asm("fma.rn.f32x2 %0, %1, %2, %3;" : "=l"(d) : "l"(a), "l"(b), "l"(c));
    return d;
}

__device__ __forceinline__ float hsum2(unsigned long long v) {
    return __uint_as_float((unsigned)v) + __uint_as_float((unsigned)(v >> 32));
}

__global__ __launch_bounds__(NT, 1) void rnn_fused_kernel(
    const float* __restrict__ x,      // [B, T, 1]
    const float* __restrict__ Wih0,   // [64, 1]
    const float* __restrict__ Whh0,   // [64, 64]
    const float* __restrict__ bih0,   // [64]
    const float* __restrict__ bhh0,   // [64]
    const float* __restrict__ Wih1,   // [64, 64]
    const float* __restrict__ Whh1,   // [64, 64]
    const float* __restrict__ bih1,   // [64]
    const float* __restrict__ bhh1,   // [64]
    const float* __restrict__ Wfc,    // [1, 64]
    const float* __restrict__ bfc,    // [1]
    float* __restrict__ out)          // [B, 1]
{
    extern __shared__ float sm[];
    float* W0  = sm;                 // Whh0 [64][HP]
    float* Wi1 = W0  + 64 * HP;      // Wih1 [64][HP]
    float* Wh1 = Wi1 + 64 * HP;      // Whh1 [64][HP]
    float* h0s = Wh1 + 64 * HP;      // [2][BB][HP] double-buffered
    float* h1s = h0s + 2 * BB * HP;  // [2][BB][HP]
    float* xs  = h1s + 2 * BB * HP;  // [BB][XS] x chunk (64 timesteps)
    float* wfc = xs  + BB * XS;      // [64]

    const int tx = threadIdx.x;
    const int b0 = blockIdx.x * BB;

    // ---- stage weights into shared (padded pitch) ----
    for (int idx = tx; idx < 64 * 64; idx += NT) {
        int r = idx >> 6, c = idx & 63;
        W0 [r * HP + c] = Whh0[idx];
        Wi1[r * HP + c] = Wih1[idx];
        Wh1[r * HP + c] = Whh1[idx];
    }
    if (tx < 64) wfc[tx] = Wfc[tx];
    for (int idx = tx; idx < 2 * BB * HP; idx += NT) {
        h0s[idx] = 0.0f;
        h1s[idx] = 0.0f;
    }

    // thread tile: warp dg owns dims {4dg..4dg+3}; within warp lane = kq*8+rq:
    // rows {rq, rq+8}, k-range [kq*16, kq*16+16). Octets span rq -> h loads
    // conflict-free; weight addresses vary only in kq -> octet broadcast.
    const int dg   = tx >> 5;        // warp id 0..15
    const int lane = tx & 31;
    const int kq   = lane >> 3;      // 0..3
    const int rq   = lane & 7;       // 0..7
    const int r0 = rq, r1 = rq + 8;
    const int d0 = 4 * dg;
    const int koff = kq * 16;

    float wx[4], b0j[4], b1j[4];
    #pragma unroll
    for (int j = 0; j < 4; ++j) {
        wx[j]  = Wih0[d0 + j];
        b0j[j] = bih0[d0 + j] + bhh0[d0 + j];
        b1j[j] = bih1[d0 + j] + bhh1[d0 + j];
    }

    __syncthreads();

    int cur = 0;
    for (int t = 0; t < Tt; ++t) {
        // refill x chunk every 64 steps (prior step's end-barrier orders this)
        if ((t & 63) == 0) {
            #pragma unroll
            for (int j = 0; j < (BB * 64) / NT; ++j) {
                int idx = tx + j * NT;
                int r = idx >> 6, c = idx & 63;
                xs[r * XS + c] = x[(b0 + r) * Tt + t + c];
            }
            __syncthreads();
        }
        const int tc = t & 63;
        const float* h0c = h0s + cur * BB * HP;
        float*       h0n = h0s + (cur ^ 1) * BB * HP;
        const float* h1c = h1s + cur * BB * HP;
        float*       h1n = h1s + (cur ^ 1) * BB * HP;

        // ---- phase 1: layer-0 step  h0' = tanh(x*wih0 + b + Whh0 h0) ----
        {
            unsigned long long a[8] = {0, 0, 0, 0, 0, 0, 0, 0};
            #pragma unroll
            for (int i = 0; i < 4; ++i) {
                ulonglong2 ha = *(const ulonglong2*)(h0c + r0 * HP + koff + 4 * i);
                ulonglong2 hb = *(const ulonglong2*)(h0c + r1 * HP + koff + 4 * i);
                #pragma unroll
                for (int j = 0; j < 4; ++j) {
                    ulonglong2 w = *(const ulonglong2*)(W0 + (d0 + j) * HP + koff + 4 * i);
                    a[j]     = fma2(ha.x, w.x, a[j]);
                    a[j]     = fma2(ha.y, w.y, a[j]);
                    a[4 + j] = fma2(hb.x, w.x, a[4 + j]);
                    a[4 + j] = fma2(hb.y, w.y, a[4 + j]);
                }
            }
            float s[8];
            #pragma unroll
            for (int m = 0; m < 8; ++m) {
                s[m] = hsum2(a[m]);
                s[m] += __shfl_xor_sync(0xffffffffu, s[m], 8);
                s[m] += __shfl_xor_sync(0xffffffffu, s[m], 16);
            }
            const float xv0 = xs[r0 * XS + tc];
            const float xv1 = xs[r1 * XS + tc];
            float4 v0, v1;
            v0.x = fast_tanhf(fmaf(xv0, wx[0], s[0] + b0j[0]));
            v0.y = fast_tanhf(fmaf(xv0, wx[1], s[1] + b0j[1]));
            v0.z = fast_tanhf(fmaf(xv0, wx[2], s[2] + b0j[2]));
            v0.w = fast_tanhf(fmaf(xv0, wx[3], s[3] + b0j[3]));
            v1.x = fast_tanhf(fmaf(xv1, wx[0], s[4] + b0j[0]));
            v1.y = fast_tanhf(fmaf(xv1, wx[1], s[5] + b0j[1]));
            v1.z = fast_tanhf(fmaf(xv1, wx[2], s[6] + b0j[2]));
            v1.w = fast_tanhf(fmaf(xv1, wx[3], s[7] + b0j[3]));
            if (kq == 0) {
                *(float4*)(h0n + r0 * HP + d0) = v0;
                *(float4*)(h0n + r1 * HP + d0) = v1;
            }
        }
        __syncthreads();

        // ---- phase 2: layer-1 step  h1' = tanh(Wih1 h0' + b + Whh1 h1) ----
        {
            unsigned long long a[8] = {0, 0, 0, 0, 0, 0, 0, 0};
            #pragma unroll
            for (int i = 0; i < 4; ++i) {
                ulonglong2 ga = *(const ulonglong2*)(h0n + r0 * HP + koff + 4 * i);
                ulonglong2 gb = *(const ulonglong2*)(h0n + r1 * HP + koff + 4 * i);
                ulonglong2 ha = *(const ulonglong2*)(h1c + r0 * HP + koff + 4 * i);
                ulonglong2 hb = *(const ulonglong2*)(h1c + r1 * HP + koff + 4 * i);
                #pragma unroll
                for (int j = 0; j < 4; ++j) {
                    ulonglong2 wi = *(const ulonglong2*)(Wi1 + (d0 + j) * HP + koff + 4 * i);
                    ulonglong2 wh = *(const ulonglong2*)(Wh1 + (d0 + j) * HP + koff + 4 * i);
                    a[j]     = fma2(ga.x, wi.x, a[j]);
                    a[j]     = fma2(ga.y, wi.y, a[j]);
                    a[j]     = fma2(ha.x, wh.x, a[j]);
                    a[j]     = fma2(ha.y, wh.y, a[j]);
                    a[4 + j] = fma2(gb.x, wi.x, a[4 + j]);
                    a[4 + j] = fma2(gb.y, wi.y, a[4 + j]);
                    a[4 + j] = fma2(hb.x, wh.x, a[4 + j]);
                    a[4 + j] = fma2(hb.y, wh.y, a[4 + j]);
                }
            }
            float s[8];
            #pragma unroll
            for (int m = 0; m < 8; ++m) {
                s[m] = hsum2(a[m]);
                s[m] += __shfl_xor_sync(0xffffffffu, s[m], 8);
                s[m] += __shfl_xor_sync(0xffffffffu, s[m], 16);
            }
            float4 v0, v1;
            v0.x = fast_tanhf(s[0] + b1j[0]);
            v0.y = fast_tanhf(s[1] + b1j[1]);
            v0.z = fast_tanhf(s[2] + b1j[2]);
            v0.w = fast_tanhf(s[3] + b1j[3]);
            v1.x = fast_tanhf(s[4] + b1j[0]);
            v1.y = fast_tanhf(s[5] + b1j[1]);
            v1.z = fast_tanhf(s[6] + b1j[2]);
            v1.w = fast_tanhf(s[7] + b1j[3]);
            if (kq == 0) {
                *(float4*)(h1n + r0 * HP + d0) = v0;
                *(float4*)(h1n + r1 * HP + d0) = v1;
            }
        }
        __syncthreads();
        cur ^= 1;
    }

    // ---- FC head: out[b] = Wfc . h1_last[b] + bfc ----
    const float* h1f = h1s + cur * BB * HP;
    if (tx < BB) {
        float acc = bfc[0];
        #pragma unroll
        for (int k = 0; k < 64; ++k)
            acc = fmaf(h1f[tx * HP + k], wfc[k], acc);
        out[b0 + tx] = acc;
    }
}

extern "C" void kernel_launch(void* const* d_in, const int* in_sizes, int n_in,
                              void* d_out, int out_size) {
    (void)in_sizes; (void)n_in; (void)out_size;
    const float* x    = (const float*)d_in[0];
    const float* Wih0 = (const float*)d_in[1];
    const float* Whh0 = (const float*)d_in[2];
    const float* bih0 = (const float*)d_in[3];
    const float* bhh0 = (const float*)d_in[4];
    const float* Wih1 = (const float*)d_in[5];
    const float* Whh1 = (const float*)d_in[6];
    const float* bih1 = (const float*)d_in[7];
    const float* bhh1 = (const float*)d_in[8];
    const float* Wfc  = (const float*)d_in[9];
    const float* bfc  = (const float*)d_in[10];
    float* out = (float*)d_out;

    constexpr int SMEM_FLOATS = 3 * 64 * HP + 4 * BB * HP + BB * XS + 64;
    constexpr int SMEM_BYTES  = SMEM_FLOATS * 4;  // 74048

    cudaFuncSetAttribute(rnn_fused_kernel,
                         cudaFuncAttributeMaxDynamicSharedMemorySize, SMEM_BYTES);

    dim3 grid(Bq / BB), block(NT);   // 128 CTAs x 512 threads
    rnn_fused_kernel<<<grid, block, SMEM_BYTES>>>(
        x, Wih0, Whh0, bih0, bhh0, Wih1, Whh1, bih1, bhh1, Wfc, bfc, out);
}

// round 11
// speedup vs baseline: 1.1914x; 1.1774x over previous
#include <cuda_runtime.h>

// UniversalRNN: 2-layer tanh RNN (B=2048, T=512, IN=1, H=64) + FC(64->1).
// R10: R5/R7 showed barrier/latency-bound (no pipe >60%, 2 barriers/step).
// Software pipeline: interval i computes h0(i) AND h1(i-1) -> ONE barrier per
// interval, independent chains interleave. h0(i-1) chunk shared by both
// phases (loaded once). BB=14 real rows, grid=147 -> all 148 SMs.

constexpr int Bq  = 2048;
constexpr int Tt  = 512;
constexpr int BBS = 16;   // row slots per CTA (padded)
constexpr int BBR = 14;   // real rows per CTA
constexpr int NT  = 512;  // threads per CTA (16 warps)
constexpr int HP  = 68;   // padded row pitch (floats)
constexpr int XS  = 65;   // x chunk row pitch

// tanh via ex2/rcp approx: ~1e-6 abs err
__device__ __forceinline__ float fast_tanhf(float x) {
    float e;
    asm("ex2.approx.f32 %0, %1;" : "=f"(e) : "f"(x * 2.8853900817779268f));
    float r;
    asm("rcp.approx.f32 %0, %1;" : "=f"(r) : "f"(e + 1.0f));
    return fmaf(-2.0f, r, 1.0f);
}

// packed 2xf32 fma (sm_100+ PTX only)
__device__ __forceinline__ unsigned long long fma2(
    unsigned long long a, unsigned long long b, unsigned long long c) {
    unsigned long long d;
    asm("fma.rn.f32x2 %0, %1, %2, %3;" : "=l"(d) : "l"(a), "l"(b), "l"(c));
    return d;
}

__device__ __forceinline__ float hsum2(unsigned long long v) {
    return __uint_as_float((unsigned)v) + __uint_as_float((unsigned)(v >> 32));
}

__global__ __launch_bounds__(NT, 1) void rnn_fused_kernel(
    const float* __restrict__ x,      // [B, T, 1]
    const float* __restrict__ Wih0,   // [64, 1]
    const float* __restrict__ Whh0,   // [64, 64]
    const float* __restrict__ bih0,   // [64]
    const float* __restrict__ bhh0,   // [64]
    const float* __restrict__ Wih1,   // [64, 64]
    const float* __restrict__ Whh1,   // [64, 64]
    const float* __restrict__ bih1,   // [64]
    const float* __restrict__ bhh1,   // [64]
    const float* __restrict__ Wfc,    // [1, 64]
    const float* __restrict__ bfc,    // [1]
    float* __restrict__ out)          // [B, 1]
{
    extern __shared__ float sm[];
    float* W0  = sm;                  // Whh0 [64][HP]
    float* Wi1 = W0  + 64 * HP;       // Wih1 [64][HP]
    float* Wh1 = Wi1 + 64 * HP;       // Whh1 [64][HP]
    float* h0s = Wh1 + 64 * HP;       // [2][BBS][HP] double-buffered
    float* h1s = h0s + 2 * BBS * HP;  // [2][BBS][HP]
    float* xs  = h1s + 2 * BBS * HP;  // [BBS][XS]
    float* wfc = xs  + BBS * XS;      // [64]

    const int tx = threadIdx.x;
    const int b0 = blockIdx.x * BBR;

    // ---- stage weights into shared ----
    for (int idx = tx; idx < 64 * 64; idx += NT) {
        int r = idx >> 6, c = idx & 63;
        W0 [r * HP + c] = Whh0[idx];
        Wi1[r * HP + c] = Wih1[idx];
        Wh1[r * HP + c] = Whh1[idx];
    }
    if (tx < 64) wfc[tx] = Wfc[tx];
    for (int idx = tx; idx < 2 * BBS * HP; idx += NT) {
        h0s[idx] = 0.0f;
        h1s[idx] = 0.0f;
    }

    // warp dg owns dims {4dg..4dg+3}; lane = kq*8+rq: rows {rq, rq+8},
    // k-range [kq*16, kq*16+16)
    const int dg   = tx >> 5;
    const int lane = tx & 31;
    const int kq   = lane >> 3;
    const int rq   = lane & 7;
    const int r0 = rq, r1 = rq + 8;
    const int d0 = 4 * dg;
    const int koff = kq * 16;

    float wx[4], b0j[4], b1j[4];
    #pragma unroll
    for (int j = 0; j < 4; ++j) {
        wx[j]  = Wih0[d0 + j];
        b0j[j] = bih0[d0 + j] + bhh0[d0 + j];
        b1j[j] = bih1[d0 + j] + bhh1[d0 + j];
    }

    __syncthreads();

    int cur = 0;
    // interval i: phaseA computes h0(i) (i<Tt), phaseB computes h1(i-1) (i>=1).
    // Both read only previous-interval state -> single barrier per interval.
    for (int i = 0; i <= Tt; ++i) {
        if ((i & 63) == 0 && i < Tt) {
            #pragma unroll
            for (int j = 0; j < (BBS * 64) / NT; ++j) {
                int idx = tx + j * NT;
                int r = idx >> 6, c = idx & 63;
                float v = 0.0f;
                if (r < BBR && b0 + r < Bq) v = x[(b0 + r) * Tt + i + c];
                xs[r * XS + c] = v;
            }
            __syncthreads();
        }
        const int tc = i & 63;
        const float* h0c = h0s + cur * BBS * HP;        // h0(i-1)
        float*       h0n = h0s + (cur ^ 1) * BBS * HP;  // h0(i)
        const float* h1c = h1s + cur * BBS * HP;        // h1(i-2)
        float*       h1n = h1s + (cur ^ 1) * BBS * HP;  // h1(i-1)

        // ---- load h0(i-1) chunk ONCE (shared by phaseA Whh0 and phaseB Wih1)
        ulonglong2 g0[4], g1[4];
        #pragma unroll
        for (int ii = 0; ii < 4; ++ii) {
            g0[ii] = *(const ulonglong2*)(h0c + r0 * HP + koff + 4 * ii);
            g1[ii] = *(const ulonglong2*)(h0c + r1 * HP + koff + 4 * ii);
        }

        // ---- phaseA fma: Whh0 . h0(i-1) ----
        unsigned long long a[8] = {0, 0, 0, 0, 0, 0, 0, 0};
        #pragma unroll
        for (int ii = 0; ii < 4; ++ii) {
            #pragma unroll
            for (int j = 0; j < 4; ++j) {
                ulonglong2 w = *(const ulonglong2*)(W0 + (d0 + j) * HP + koff + 4 * ii);
                a[j]     = fma2(g0[ii].x, w.x, a[j]);
                a[j]     = fma2(g0[ii].y, w.y, a[j]);
                a[4 + j] = fma2(g1[ii].x, w.x, a[4 + j]);
                a[4 + j] = fma2(g1[ii].y, w.y, a[4 + j]);
            }
        }

        // ---- phaseB fma: Whh1 . h1(i-2) + Wih1 . h0(i-1) ----
        unsigned long long c[8] = {0, 0, 0, 0, 0, 0, 0, 0};
        #pragma unroll
        for (int ii = 0; ii < 4; ++ii) {
            ulonglong2 q0 = *(const ulonglong2*)(h1c + r0 * HP + koff + 4 * ii);
            ulonglong2 q1 = *(const ulonglong2*)(h1c + r1 * HP + koff + 4 * ii);
            #pragma unroll
            for (int j = 0; j < 4; ++j) {
                ulonglong2 wh = *(const ulonglong2*)(Wh1 + (d0 + j) * HP + koff + 4 * ii);
                c[j]     = fma2(q0.x, wh.x, c[j]);
                c[j]     = fma2(q0.y, wh.y, c[j]);
                c[4 + j] = fma2(q1.x, wh.x, c[4 + j]);
                c[4 + j] = fma2(q1.y, wh.y, c[4 + j]);
            }
        }
        #pragma unroll
        for (int ii = 0; ii < 4; ++ii) {
            #pragma unroll
            for (int j = 0; j < 4; ++j) {
                ulonglong2 wi = *(const ulonglong2*)(Wi1 + (d0 + j) * HP + koff + 4 * ii);
                c[j]     = fma2(g0[ii].x, wi.x, c[j]);
                c[j]     = fma2(g0[ii].y, wi.y, c[j]);
                c[4 + j] = fma2(g1[ii].x, wi.x, c[4 + j]);
                c[4 + j] = fma2(g1[ii].y, wi.y, c[4 + j]);
            }
        }

        // ---- phaseA reduce + tanh + store h0(i) ----
        {
            float s[8];
            #pragma unroll
            for (int m = 0; m < 8; ++m) {
                s[m] = hsum2(a[m]);
                s[m] += __shfl_xor_sync(0xffffffffu, s[m], 8);
                s[m] += __shfl_xor_sync(0xffffffffu, s[m], 16);
            }
            const float xv0 = xs[r0 * XS + tc];
            const float xv1 = xs[r1 * XS + tc];
            float4 v0, v1;
            v0.x = fast_tanhf(fmaf(xv0, wx[0], s[0] + b0j[0]));
            v0.y = fast_tanhf(fmaf(xv0, wx[1], s[1] + b0j[1]));
            v0.z = fast_tanhf(fmaf(xv0, wx[2], s[2] + b0j[2]));
            v0.w = fast_tanhf(fmaf(xv0, wx[3], s[3] + b0j[3]));
            v1.x = fast_tanhf(fmaf(xv1, wx[0], s[4] + b0j[0]));
            v1.y = fast_tanhf(fmaf(xv1, wx[1], s[5] + b0j[1]));
            v1.z = fast_tanhf(fmaf(xv1, wx[2], s[6] + b0j[2]));
            v1.w = fast_tanhf(fmaf(xv1, wx[3], s[7] + b0j[3]));
            if (kq == 0) {
                *(float4*)(h0n + r0 * HP + d0) = v0;
                *(float4*)(h0n + r1 * HP + d0) = v1;
            }
        }

        // ---- phaseB reduce + tanh + store h1(i-1) (skip at i==0) ----
        {
            float s[8];
            #pragma unroll
            for (int m = 0; m < 8; ++m) {
                s[m] = hsum2(c[m]);
                s[m] += __shfl_xor_sync(0xffffffffu, s[m], 8);
                s[m] += __shfl_xor_sync(0xffffffffu, s[m], 16);
            }
            float4 v0, v1;
            v0.x = fast_tanhf(s[0] + b1j[0]);
            v0.y = fast_tanhf(s[1] + b1j[1]);
            v0.z = fast_tanhf(s[2] + b1j[2]);
            v0.w = fast_tanhf(s[3] + b1j[3]);
            v1.x = fast_tanhf(s[4] + b1j[0]);
            v1.y = fast_tanhf(s[5] + b1j[1]);
            v1.z = fast_tanhf(s[6] + b1j[2]);
            v1.w = fast_tanhf(s[7] + b1j[3]);
            if (i != 0 && kq == 0) {
                *(float4*)(h1n + r0 * HP + d0) = v0;
                *(float4*)(h1n + r1 * HP + d0) = v1;
            }
        }
        __syncthreads();
        cur ^= 1;
    }

    // ---- FC head: out[b] = Wfc . h1(Tt-1)[b] + bfc ----
    const float* h1f = h1s + cur * BBS * HP;
    if (tx < BBR && b0 + tx < Bq) {
        float acc = bfc[0];
        #pragma unroll
        for (int k = 0; k < 64; ++k)
            acc = fmaf(h1f[tx * HP + k], wfc[k], acc);
        out[b0 + tx] = acc;
    }
}

extern "C" void kernel_launch(void* const* d_in, const int* in_sizes, int n_in,
                              void* d_out, int out_size) {
    (void)in_sizes; (void)n_in; (void)out_size;
    const float* x    = (const float*)d_in[0];
    const float* Wih0 = (const float*)d_in[1];
    const float* Whh0 = (const float*)d_in[2];
    const float* bih0 = (const float*)d_in[3];
    const float* bhh0 = (const float*)d_in[4];
    const float* Wih1 = (const float*)d_in[5];
    const float* Whh1 = (const float*)d_in[6];
    const float* bih1 = (const float*)d_in[7];
    const float* bhh1 = (const float*)d_in[8];
    const float* Wfc  = (const float*)d_in[9];
    const float* bfc  = (const float*)d_in[10];
    float* out = (float*)d_out;

    constexpr int SMEM_FLOATS = 3 * 64 * HP + 4 * BBS * HP + BBS * XS + 64;
    constexpr int SMEM_BYTES  = SMEM_FLOATS * 4;

    cudaFuncSetAttribute(rnn_fused_kernel,
                         cudaFuncAttributeMaxDynamicSharedMemorySize, SMEM_BYTES);

    constexpr int GRID = (Bq + BBR - 1) / BBR;  // 147 CTAs -> all SMs
    rnn_fused_kernel<<<GRID, NT, SMEM_BYTES>>>(
        x, Wih0, Whh0, bih0, bhh0, Wih1, Whh1, bih1, bhh1, Wfc, bfc, out);
}